// round 11
// baseline (speedup 1.0000x reference)
#include <cuda_runtime.h>
#include <cstdint>
#include <math.h>

#define S_LEN 2048
#define HID   1024
#define NH    16
#define HD    64
#define BATCH 2
#define ROWS  (BATCH * S_LEN)   // 4096
#define NT    (S_LEN / 128)     // 16 q-tiles

typedef unsigned long long u64;

// -------- scratch (static __device__ arrays; no allocation allowed) --------
__device__ float g_qkv[(size_t)ROWS * 3 * HID];  // [4096][3072]
__device__ float g_att[(size_t)ROWS * HID];      // [4096][1024]
__device__ float g_cos[S_LEN * 32];
__device__ float g_sin[S_LEN * 32];

// ======================= packed f32x2 helpers ==============================
__device__ __forceinline__ u64 pack2(float x, float y) {
    u64 r; asm("mov.b64 %0, {%1,%2};" : "=l"(r) : "f"(x), "f"(y)); return r;
}
__device__ __forceinline__ void fma2(u64& d, u64 a, u64 b) {
    asm("fma.rn.f32x2 %0, %1, %2, %0;" : "+l"(d) : "l"(a), "l"(b));
}
__device__ __forceinline__ u64 mul2(u64 a, u64 b) {
    u64 r; asm("mul.rn.f32x2 %0, %1, %2;" : "=l"(r) : "l"(a), "l"(b)); return r;
}
__device__ __forceinline__ float2 unpack2(u64 v) {
    float2 r; asm("mov.b64 {%0,%1}, %2;" : "=f"(r.x), "=f"(r.y) : "l"(v)); return r;
}
__device__ __forceinline__ float ex2(float x) {
    float r; asm("ex2.approx.f32 %0, %1;" : "=f"(r) : "f"(x)); return r;
}
__device__ __forceinline__ uint32_t smem_u32(const void* p) {
    uint32_t a;
    asm("{ .reg .u64 t; cvta.to.shared.u64 t, %1; cvt.u32.u64 %0, t; }" : "=r"(a) : "l"(p));
    return a;
}
__device__ __forceinline__ void cp_async16(uint32_t dst, const void* src) {
    asm volatile("cp.async.cg.shared.global [%0], [%1], 16;" :: "r"(dst), "l"(src) : "memory");
}
#define CP_COMMIT() asm volatile("cp.async.commit_group;" ::: "memory")
#define CP_WAIT0()  asm volatile("cp.async.wait_group 0;" ::: "memory")

// ================ f32x2 SGEMM v6 (cp.async, 1 sync/tile) ===================
// C[M,N]=A[M,K]*B[K,N] row-major. 128x128 tile, BK=16, double-buffered.
// B: gmem->smem via cp.async (swizzled chunk map). A: LDG->regs->STS (transpose).
__global__ __launch_bounds__(256, 2) void sgemm6(
    const float* __restrict__ A, const float* __restrict__ B,
    float* __restrict__ C, int M, int N, int K)
{
    __shared__ __align__(16) float As[2][16][132];
    __shared__ __align__(16) float Bs[2][16][128];

    const int tid = threadIdx.x;
    const int tx = tid & 15, ty = tid >> 4;
    const int m0 = blockIdx.y * 128, n0 = blockIdx.x * 128;
    const int s2 = ((tx >> 2) & 1) << 2;

    const int ar = tid & 127, akc = (tid >> 7) << 3;
    const float* Agp = A + (size_t)(m0 + ar) * K + akc;

    // cp.async B chunk map: 512 16B-chunks per tile, 2 per thread
    const int brow0 = tid >> 5,          bc40 = tid & 31;
    const int brow1 = (tid + 256) >> 5,  bc41 = tid & 31;   // tid+256: same &31
    const int bd0 = (bc40 ^ ((bc40 >> 3) & 1)) << 2;
    const int bd1 = (bc41 ^ ((bc41 >> 3) & 1)) << 2;
    uint32_t bdst[2][2];
    bdst[0][0] = smem_u32(&Bs[0][brow0][bd0]);
    bdst[0][1] = smem_u32(&Bs[0][brow1][bd1]);
    bdst[1][0] = smem_u32(&Bs[1][brow0][bd0]);
    bdst[1][1] = smem_u32(&Bs[1][brow1][bd1]);
    const float* Bg0 = B + (size_t)brow0 * N + n0 + bc40 * 4;
    const float* Bg1 = B + (size_t)brow1 * N + n0 + bc41 * 4;

    u64 acc[8][4];
#pragma unroll
    for (int r = 0; r < 8; r++)
#pragma unroll
        for (int c = 0; c < 4; c++) acc[r][c] = pack2(0.f, 0.f);

    const int T = K >> 4;

    // prologue: A(0) -> regs, B(0) -> stage0 via cp.async
    float4 pa0 = *(const float4*)(Agp);
    float4 pa1 = *(const float4*)(Agp + 4);
    cp_async16(bdst[0][0], Bg0);
    cp_async16(bdst[0][1], Bg1);
    CP_COMMIT();

    for (int t = 0; t < T; t++) {
        const int s = t & 1;
        // STS A(t) (buf s last read at compute(t-2); sync(t-1) closed it)
        {
            const float av[8] = {pa0.x, pa0.y, pa0.z, pa0.w, pa1.x, pa1.y, pa1.z, pa1.w};
#pragma unroll
            for (int e = 0; e < 8; e++) As[s][akc + e][ar] = av[e];
        }
        CP_WAIT0();            // B(t) DMA complete
        __syncthreads();       // A(t)/B(t) visible; compute(t-1) fully retired

        if (t + 1 < T) {       // issue loads for t+1 (hidden under compute(t))
            const int k0 = (t + 1) << 4;
            pa0 = *(const float4*)(Agp + k0);
            pa1 = *(const float4*)(Agp + k0 + 4);
            const float* Bsrc = B + (size_t)k0 * N;
            cp_async16(bdst[s ^ 1][0], Bsrc + (Bg0 - B));
            cp_async16(bdst[s ^ 1][1], Bsrc + (Bg1 - B));
            CP_COMMIT();
        }

#pragma unroll
        for (int kk = 0; kk < 16; kk++) {
            float4 a0 = *(const float4*)&As[s][kk][ty * 8];
            float4 a1 = *(const float4*)&As[s][kk][ty * 8 + 4];
            float4 b0 = *(const float4*)&Bs[s][kk][(tx * 8) ^ s2];
            float4 b1 = *(const float4*)&Bs[s][kk][(tx * 8 + 4) ^ s2];
            u64 bp[4] = {pack2(b0.x, b0.y), pack2(b0.z, b0.w),
                         pack2(b1.x, b1.y), pack2(b1.z, b1.w)};
            const float av[8] = {a0.x, a0.y, a0.z, a0.w, a1.x, a1.y, a1.z, a1.w};
#pragma unroll
            for (int r = 0; r < 8; r++) {
                u64 ap = pack2(av[r], av[r]);
#pragma unroll
                for (int c = 0; c < 4; c++) fma2(acc[r][c], ap, bp[c]);
            }
        }
    }

#pragma unroll
    for (int r = 0; r < 8; r++) {
        float* crow = C + (size_t)(m0 + ty * 8 + r) * N + n0 + tx * 8;
        float2 v0 = unpack2(acc[r][0]), v1 = unpack2(acc[r][1]);
        float2 v2 = unpack2(acc[r][2]), v3 = unpack2(acc[r][3]);
        *(float4*)(crow)     = make_float4(v0.x, v0.y, v1.x, v1.y);
        *(float4*)(crow + 4) = make_float4(v2.x, v2.y, v3.x, v3.y);
    }
}

// ============================ RoPE tables ==================================
__global__ void rope_tables_kernel()
{
    int idx = blockIdx.x * blockDim.x + threadIdx.x;
    if (idx >= S_LEN * 32) return;
    int s = idx >> 5, j = idx & 31;
    double inv = exp(-((double)j / 32.0) * log(160000.0));
    double ang = (double)s * inv;
    g_cos[idx] = (float)cos(ang);
    g_sin[idx] = (float)sin(ang);
}

// ======================= RoPE apply (in-place on qkv) ======================
__global__ __launch_bounds__(256) void rope_apply_kernel()
{
    int idx = blockIdx.x * blockDim.x + threadIdx.x;
    if (idx >= ROWS * 1024) return;
    int row  = idx >> 10;
    int rem  = idx & 1023;
    int t    = rem >> 9;
    int rem2 = rem & 511;
    int h    = rem2 >> 5;
    int j    = rem2 & 31;
    int s    = row & (S_LEN - 1);

    size_t base = (size_t)row * 3072 + (size_t)t * HID + h * HD;
    float x1 = g_qkv[base + j];
    float x2 = g_qkv[base + j + 32];
    float c  = g_cos[s * 32 + j];
    float sn = g_sin[s * 32 + j];
    g_qkv[base + j]      = x1 * c - x2 * sn;
    g_qkv[base + j + 32] = x2 * c + x1 * sn;
}

// ===== fused causal flash attention v5 (balanced + log2-domain softmax) ====
#define AQT 0
#define AKT 8192
#define AVS 12288
#define APT 16640
#define ATTN_F 24832          // 99328 bytes
#define QSCALE 0.18033688f    // 0.125 * log2(e)

__global__ __launch_bounds__(256, 2) void attn5_kernel(
    const float* __restrict__ qkv, float* __restrict__ out)
{
    extern __shared__ __align__(16) float sm[];
    float* Qt = sm + AQT;
    float* Kt = sm + AKT;
    float* Vs = sm + AVS;
    float* Pt = sm + APT;

    const int tid = threadIdx.x;
    const int tx = tid & 7, ty = tid >> 3;
    const int i0 = ty * 4, c0 = tx * 8;
    const int sK = (tx >> 2) << 2;
    const int bh = blockIdx.y;
    const int b = bh >> 4, h = bh & 15;
    const size_t rowbase = (size_t)b * S_LEN;
    const int qoff = h * HD, koff = HID + h * HD, voff = 2 * HID + h * HD;

    const int frq = tid & 127, fgq = tid >> 7;
    const int fr = tid & 63, fg = tid >> 6;
    const int jswz = fr ^ ((((fr >> 5) & 1)) << 2);
    const int vcs  = (fg >> 1) << 2;

#pragma unroll 1
    for (int pass = 0; pass < 2; pass++) {
        const int qt = pass ? (NT - 1 - (int)blockIdx.x) : (int)blockIdx.x;
        const int q0 = qt * 128;

        // Q fill, pre-scaled by 0.125*log2e (softmax runs in log2 domain)
        {
            const float* qp = qkv + (rowbase + q0 + frq) * 3072 + qoff + fgq * 32;
#pragma unroll
            for (int q = 0; q < 8; q++) {
                float4 v = *(const float4*)(qp + 4 * q);
                int d = fgq * 32 + 4 * q;
                Qt[(d + 0) * 128 + frq] = v.x * QSCALE;
                Qt[(d + 1) * 128 + frq] = v.y * QSCALE;
                Qt[(d + 2) * 128 + frq] = v.z * QSCALE;
                Qt[(d + 3) * 128 + frq] = v.w * QSCALE;
            }
        }

        float mreg[4], lreg[4], alpha[4];
        u64 O[4][4];
#pragma unroll
        for (int r = 0; r < 4; r++) {
            mreg[r] = -INFINITY; lreg[r] = 0.f;
#pragma unroll
            for (int c = 0; c < 4; c++) O[r][c] = pack2(0.f, 0.f);
        }

        for (int j0 = 0; j0 <= q0 + 64; j0 += 64) {
            __syncthreads();
            {
                const float* kp = qkv + (rowbase + j0 + fr) * 3072 + koff + fg * 16;
#pragma unroll
                for (int q = 0; q < 4; q++) {
                    float4 v = *(const float4*)(kp + 4 * q);
                    int d = fg * 16 + 4 * q;
                    Kt[(d + 0) * 64 + jswz] = v.x; Kt[(d + 1) * 64 + jswz] = v.y;
                    Kt[(d + 2) * 64 + jswz] = v.z; Kt[(d + 3) * 64 + jswz] = v.w;
                }
                const float* vp = qkv + (rowbase + j0 + fr) * 3072 + voff + fg * 16;
#pragma unroll
                for (int q = 0; q < 4; q++) {
                    int c = fg * 16 + 4 * q;
                    *(float4*)&Vs[fr * 68 + (c ^ vcs)] = *(const float4*)(vp + 4 * q);
                }
            }
            __syncthreads();

            u64 sac[4][4];
#pragma unroll
            for (int r = 0; r < 4; r++)
#pragma unroll
                for (int c = 0; c < 4; c++) sac[r][c] = pack2(0.f, 0.f);
#pragma unroll 4
            for (int d = 0; d < 64; d++) {
                float4 qv = *(const float4*)&Qt[d * 128 + i0];
                ulonglong2 k0 = *(const ulonglong2*)&Kt[d * 64 + (c0 ^ sK)];
                ulonglong2 k1 = *(const ulonglong2*)&Kt[d * 64 + ((c0 + 4) ^ sK)];
                const float qa[4] = {qv.x, qv.y, qv.z, qv.w};
#pragma unroll
                for (int r = 0; r < 4; r++) {
                    u64 qp2 = pack2(qa[r], qa[r]);
                    fma2(sac[r][0], qp2, k0.x);
                    fma2(sac[r][1], qp2, k0.y);
                    fma2(sac[r][2], qp2, k1.x);
                    fma2(sac[r][3], qp2, k1.y);
                }
            }

            const bool maskt = (j0 + 63 > q0);
            float ps[4][8];
#pragma unroll
            for (int r = 0; r < 4; r++) {
                float sv[8];
#pragma unroll
                for (int c = 0; c < 4; c++) {
                    float2 v = unpack2(sac[r][c]);
                    sv[2 * c] = v.x; sv[2 * c + 1] = v.y;   // already log2-scaled
                }
                if (maskt) {
                    int rowg = q0 + i0 + r;
#pragma unroll
                    for (int cc = 0; cc < 8; cc++)
                        if (j0 + c0 + cc > rowg) sv[cc] = -1e9f;
                }
                float ml = sv[0];
#pragma unroll
                for (int cc = 1; cc < 8; cc++) ml = fmaxf(ml, sv[cc]);
                ml = fmaxf(ml, __shfl_xor_sync(0xffffffffu, ml, 1));
                ml = fmaxf(ml, __shfl_xor_sync(0xffffffffu, ml, 2));
                ml = fmaxf(ml, __shfl_xor_sync(0xffffffffu, ml, 4));
                float mn = fmaxf(mreg[r], ml);
                float a = ex2(mreg[r] - mn);
                mreg[r] = mn; alpha[r] = a;
                float rs = 0.f;
#pragma unroll
                for (int cc = 0; cc < 8; cc++) { ps[r][cc] = ex2(sv[cc] - mn); rs += ps[r][cc]; }
                rs += __shfl_xor_sync(0xffffffffu, rs, 1);
                rs += __shfl_xor_sync(0xffffffffu, rs, 2);
                rs += __shfl_xor_sync(0xffffffffu, rs, 4);
                lreg[r] = lreg[r] * a + rs;
            }
            {
                const int ip = i0 ^ (tx << 2);
#pragma unroll
                for (int cc = 0; cc < 8; cc++)
                    *(float4*)&Pt[(c0 + cc) * 128 + ip] =
                        make_float4(ps[0][cc], ps[1][cc], ps[2][cc], ps[3][cc]);
            }
#pragma unroll
            for (int r = 0; r < 4; r++) {
                u64 a2 = pack2(alpha[r], alpha[r]);
#pragma unroll
                for (int c = 0; c < 4; c++) O[r][c] = mul2(O[r][c], a2);
            }
            __syncthreads();

#pragma unroll
            for (int jo = 0; jo < 8; jo++) {
                const int sp = jo << 2;
#pragma unroll
                for (int ji = 0; ji < 8; ji++) {
                    const int j = jo * 8 + ji;
                    float4 pv = *(const float4*)&Pt[j * 128 + (i0 ^ sp)];
                    ulonglong2 v0 = *(const ulonglong2*)&Vs[j * 68 + (c0 ^ sK)];
                    ulonglong2 v1 = *(const ulonglong2*)&Vs[j * 68 + ((c0 + 4) ^ sK)];
                    const float pa[4] = {pv.x, pv.y, pv.z, pv.w};
#pragma unroll
                    for (int r = 0; r < 4; r++) {
                        u64 pp = pack2(pa[r], pa[r]);
                        fma2(O[r][0], pp, v0.x);
                        fma2(O[r][1], pp, v0.y);
                        fma2(O[r][2], pp, v1.x);
                        fma2(O[r][3], pp, v1.y);
                    }
                }
            }
        }

#pragma unroll
        for (int r = 0; r < 4; r++) {
            float linv = 1.0f / lreg[r];
            float2 v0 = unpack2(O[r][0]), v1 = unpack2(O[r][1]);
            float2 v2 = unpack2(O[r][2]), v3 = unpack2(O[r][3]);
            float* op = out + (rowbase + q0 + i0 + r) * HID + h * HD + c0;
            *(float4*)(op)     = make_float4(v0.x * linv, v0.y * linv, v1.x * linv, v1.y * linv);
            *(float4*)(op + 4) = make_float4(v2.x * linv, v2.y * linv, v3.x * linv, v3.y * linv);
        }
    }
}

// ================================ launch ===================================
extern "C" void kernel_launch(void* const* d_in, const int* in_sizes, int n_in,
                              void* d_out, int out_size)
{
    const float* hidden = (const float*)d_in[0];
    const float* Wqkv = (const float*)d_in[2];
    const float* Wo   = (const float*)d_in[3];
    float* out = (float*)d_out;

    float *qkv_ptr, *att_ptr;
    cudaGetSymbolAddress((void**)&qkv_ptr, g_qkv);
    cudaGetSymbolAddress((void**)&att_ptr, g_att);

    rope_tables_kernel<<<(S_LEN * 32 + 255) / 256, 256>>>();

    sgemm6<<<dim3(3 * HID / 128, ROWS / 128), 256>>>(hidden, Wqkv, qkv_ptr, ROWS, 3 * HID, HID);

    rope_apply_kernel<<<(ROWS * 1024) / 256, 256>>>();

    const int SMEM = ATTN_F * 4;
    cudaFuncSetAttribute(attn5_kernel, cudaFuncAttributeMaxDynamicSharedMemorySize, SMEM);
    dim3 g2(NT / 2, BATCH * NH);
    attn5_kernel<<<g2, 256, SMEM>>>(qkv_ptr, att_ptr);

    sgemm6<<<dim3(HID / 128, ROWS / 128), 256>>>(att_ptr, Wo, out, ROWS, HID, HID);
}

// round 12
// speedup vs baseline: 1.0080x; 1.0080x over previous
#include <cuda_runtime.h>
#include <cstdint>
#include <math.h>

#define S_LEN 2048
#define HID   1024
#define NH    16
#define HD    64
#define BATCH 2
#define ROWS  (BATCH * S_LEN)   // 4096
#define NT    (S_LEN / 128)     // 16 q-tiles

typedef unsigned long long u64;

// -------- scratch (static __device__ arrays; no allocation allowed) --------
__device__ float g_qkv[(size_t)ROWS * 3 * HID];  // [4096][3072]
__device__ float g_att[(size_t)ROWS * HID];      // [4096][1024]
__device__ float g_cos[S_LEN * 32];
__device__ float g_sin[S_LEN * 32];

// ======================= packed f32x2 helpers ==============================
__device__ __forceinline__ u64 pack2(float x, float y) {
    u64 r; asm("mov.b64 %0, {%1,%2};" : "=l"(r) : "f"(x), "f"(y)); return r;
}
__device__ __forceinline__ void fma2(u64& d, u64 a, u64 b) {
    asm("fma.rn.f32x2 %0, %1, %2, %0;" : "+l"(d) : "l"(a), "l"(b));
}
__device__ __forceinline__ u64 mul2(u64 a, u64 b) {
    u64 r; asm("mul.rn.f32x2 %0, %1, %2;" : "=l"(r) : "l"(a), "l"(b)); return r;
}
__device__ __forceinline__ float2 unpack2(u64 v) {
    float2 r; asm("mov.b64 {%0,%1}, %2;" : "=f"(r.x), "=f"(r.y) : "l"(v)); return r;
}
__device__ __forceinline__ float ex2(float x) {
    float r; asm("ex2.approx.f32 %0, %1;" : "=f"(r) : "f"(x)); return r;
}

// ============= f32x2 SGEMM v7 (double-buffered, 1 sync/tile) ===============
// C[M,N]=A[M,K]*B[K,N] row-major. 128x128 tile, BK=16.
// iter t: LDG(t+1)->regs; compute(t) from buf s; STS(t+1)->buf s^1; sync.
__global__ __launch_bounds__(256, 2) void sgemm7(
    const float* __restrict__ A, const float* __restrict__ B,
    float* __restrict__ C, int M, int N, int K)
{
    __shared__ __align__(16) float As[2][16][132];
    __shared__ __align__(16) float Bs[2][16][128];

    const int tid = threadIdx.x;
    const int tx = tid & 15, ty = tid >> 4;
    const int m0 = blockIdx.y * 128, n0 = blockIdx.x * 128;
    const int s2 = ((tx >> 2) & 1) << 2;

    const int ar = tid & 127, akc = (tid >> 7) << 3;
    const int br = tid >> 5,  bnc = (tid & 31) << 2;
    const int bns = bnc ^ ((((bnc >> 5) & 1)) << 2);
    const float* Agp = A + (size_t)(m0 + ar) * K + akc;
    const float* Bgp = B + (size_t)br * N + n0 + bnc;

    u64 acc[8][4];
#pragma unroll
    for (int r = 0; r < 8; r++)
#pragma unroll
        for (int c = 0; c < 4; c++) acc[r][c] = pack2(0.f, 0.f);

    float4 pa0, pa1, pb0, pb1;
    const int T = K >> 4;

    // prologue: load + store tile 0 into buf 0
    pa0 = *(const float4*)(Agp);
    pa1 = *(const float4*)(Agp + 4);
    pb0 = *(const float4*)(Bgp);
    pb1 = *(const float4*)(Bgp + (size_t)8 * N);
    {
        const float av[8] = {pa0.x, pa0.y, pa0.z, pa0.w, pa1.x, pa1.y, pa1.z, pa1.w};
#pragma unroll
        for (int e = 0; e < 8; e++) As[0][akc + e][ar] = av[e];
        *(float4*)&Bs[0][br][bns]     = pb0;
        *(float4*)&Bs[0][br + 8][bns] = pb1;
    }
    __syncthreads();

    for (int t = 0; t < T; t++) {
        const int s = t & 1;
        const bool more = (t + 1 < T);
        if (more) {                      // LDG(t+1): consumed by STS after compute
            const int k0 = (t + 1) << 4;
            pa0 = *(const float4*)(Agp + k0);
            pa1 = *(const float4*)(Agp + k0 + 4);
            pb0 = *(const float4*)(Bgp + (size_t)k0 * N);
            pb1 = *(const float4*)(Bgp + (size_t)(k0 + 8) * N);
        }

        // compute tile t from buf s
#pragma unroll
        for (int kk = 0; kk < 16; kk++) {
            float4 a0 = *(const float4*)&As[s][kk][ty * 8];
            float4 a1 = *(const float4*)&As[s][kk][ty * 8 + 4];
            float4 b0 = *(const float4*)&Bs[s][kk][(tx * 8) ^ s2];
            float4 b1 = *(const float4*)&Bs[s][kk][(tx * 8 + 4) ^ s2];
            u64 bp[4] = {pack2(b0.x, b0.y), pack2(b0.z, b0.w),
                         pack2(b1.x, b1.y), pack2(b1.z, b1.w)};
            const float av[8] = {a0.x, a0.y, a0.z, a0.w, a1.x, a1.y, a1.z, a1.w};
#pragma unroll
            for (int r = 0; r < 8; r++) {
                u64 ap = pack2(av[r], av[r]);
#pragma unroll
                for (int c = 0; c < 4; c++) fma2(acc[r][c], ap, bp[c]);
            }
        }

        if (more) {                      // STS(t+1) -> other buffer
            const float av[8] = {pa0.x, pa0.y, pa0.z, pa0.w, pa1.x, pa1.y, pa1.z, pa1.w};
#pragma unroll
            for (int e = 0; e < 8; e++) As[s ^ 1][akc + e][ar] = av[e];
            *(float4*)&Bs[s ^ 1][br][bns]     = pb0;
            *(float4*)&Bs[s ^ 1][br + 8][bns] = pb1;
            __syncthreads();
        }
    }

#pragma unroll
    for (int r = 0; r < 8; r++) {
        float* crow = C + (size_t)(m0 + ty * 8 + r) * N + n0 + tx * 8;
        float2 v0 = unpack2(acc[r][0]), v1 = unpack2(acc[r][1]);
        float2 v2 = unpack2(acc[r][2]), v3 = unpack2(acc[r][3]);
        *(float4*)(crow)     = make_float4(v0.x, v0.y, v1.x, v1.y);
        *(float4*)(crow + 4) = make_float4(v2.x, v2.y, v3.x, v3.y);
    }
}

// ============================ RoPE tables ==================================
__global__ void rope_tables_kernel()
{
    int idx = blockIdx.x * blockDim.x + threadIdx.x;
    if (idx >= S_LEN * 32) return;
    int s = idx >> 5, j = idx & 31;
    double inv = exp(-((double)j / 32.0) * log(160000.0));
    double ang = (double)s * inv;
    g_cos[idx] = (float)cos(ang);
    g_sin[idx] = (float)sin(ang);
}

// ================== RoPE apply v2 (float4-vectorized) ======================
// thread: (row, q|k, head, j-quad). LDG.128/STG.128 throughout.
__global__ __launch_bounds__(256) void rope_apply2_kernel()
{
    int idx = blockIdx.x * blockDim.x + threadIdx.x;   // ROWS*256 threads
    if (idx >= ROWS * 256) return;
    int row = idx >> 8;
    int rem = idx & 255;
    int t   = rem >> 7;           // 0=q, 1=k
    int h   = (rem >> 3) & 15;
    int j   = (rem & 7) << 2;
    int s   = row & (S_LEN - 1);

    float* p = g_qkv + (size_t)row * 3072 + (size_t)t * HID + h * HD;
    float4 x1 = *(float4*)(p + j);
    float4 x2 = *(float4*)(p + j + 32);
    float4 c  = *(const float4*)(g_cos + s * 32 + j);
    float4 sn = *(const float4*)(g_sin + s * 32 + j);

    float4 o1, o2;
    o1.x = x1.x * c.x - x2.x * sn.x;  o2.x = x2.x * c.x + x1.x * sn.x;
    o1.y = x1.y * c.y - x2.y * sn.y;  o2.y = x2.y * c.y + x1.y * sn.y;
    o1.z = x1.z * c.z - x2.z * sn.z;  o2.z = x2.z * c.z + x1.z * sn.z;
    o1.w = x1.w * c.w - x2.w * sn.w;  o2.w = x2.w * c.w + x1.w * sn.w;
    *(float4*)(p + j)      = o1;
    *(float4*)(p + j + 32) = o2;
}

// ===== fused causal flash attention v5 (balanced + log2-domain softmax) ====
#define AQT 0
#define AKT 8192
#define AVS 12288
#define APT 16640
#define ATTN_F 24832          // 99328 bytes
#define QSCALE 0.18033688f    // 0.125 * log2(e)

__global__ __launch_bounds__(256, 2) void attn5_kernel(
    const float* __restrict__ qkv, float* __restrict__ out)
{
    extern __shared__ __align__(16) float sm[];
    float* Qt = sm + AQT;
    float* Kt = sm + AKT;
    float* Vs = sm + AVS;
    float* Pt = sm + APT;

    const int tid = threadIdx.x;
    const int tx = tid & 7, ty = tid >> 3;
    const int i0 = ty * 4, c0 = tx * 8;
    const int sK = (tx >> 2) << 2;
    const int bh = blockIdx.y;
    const int b = bh >> 4, h = bh & 15;
    const size_t rowbase = (size_t)b * S_LEN;
    const int qoff = h * HD, koff = HID + h * HD, voff = 2 * HID + h * HD;

    const int frq = tid & 127, fgq = tid >> 7;
    const int fr = tid & 63, fg = tid >> 6;
    const int jswz = fr ^ ((((fr >> 5) & 1)) << 2);
    const int vcs  = (fg >> 1) << 2;

#pragma unroll 1
    for (int pass = 0; pass < 2; pass++) {
        const int qt = pass ? (NT - 1 - (int)blockIdx.x) : (int)blockIdx.x;
        const int q0 = qt * 128;

        // Q fill, pre-scaled by 0.125*log2e (softmax runs in log2 domain)
        {
            const float* qp = qkv + (rowbase + q0 + frq) * 3072 + qoff + fgq * 32;
#pragma unroll
            for (int q = 0; q < 8; q++) {
                float4 v = *(const float4*)(qp + 4 * q);
                int d = fgq * 32 + 4 * q;
                Qt[(d + 0) * 128 + frq] = v.x * QSCALE;
                Qt[(d + 1) * 128 + frq] = v.y * QSCALE;
                Qt[(d + 2) * 128 + frq] = v.z * QSCALE;
                Qt[(d + 3) * 128 + frq] = v.w * QSCALE;
            }
        }

        float mreg[4], lreg[4], alpha[4];
        u64 O[4][4];
#pragma unroll
        for (int r = 0; r < 4; r++) {
            mreg[r] = -INFINITY; lreg[r] = 0.f;
#pragma unroll
            for (int c = 0; c < 4; c++) O[r][c] = pack2(0.f, 0.f);
        }

        for (int j0 = 0; j0 <= q0 + 64; j0 += 64) {
            __syncthreads();
            {
                const float* kp = qkv + (rowbase + j0 + fr) * 3072 + koff + fg * 16;
#pragma unroll
                for (int q = 0; q < 4; q++) {
                    float4 v = *(const float4*)(kp + 4 * q);
                    int d = fg * 16 + 4 * q;
                    Kt[(d + 0) * 64 + jswz] = v.x; Kt[(d + 1) * 64 + jswz] = v.y;
                    Kt[(d + 2) * 64 + jswz] = v.z; Kt[(d + 3) * 64 + jswz] = v.w;
                }
                const float* vp = qkv + (rowbase + j0 + fr) * 3072 + voff + fg * 16;
#pragma unroll
                for (int q = 0; q < 4; q++) {
                    int c = fg * 16 + 4 * q;
                    *(float4*)&Vs[fr * 68 + (c ^ vcs)] = *(const float4*)(vp + 4 * q);
                }
            }
            __syncthreads();

            u64 sac[4][4];
#pragma unroll
            for (int r = 0; r < 4; r++)
#pragma unroll
                for (int c = 0; c < 4; c++) sac[r][c] = pack2(0.f, 0.f);
#pragma unroll 4
            for (int d = 0; d < 64; d++) {
                float4 qv = *(const float4*)&Qt[d * 128 + i0];
                ulonglong2 k0 = *(const ulonglong2*)&Kt[d * 64 + (c0 ^ sK)];
                ulonglong2 k1 = *(const ulonglong2*)&Kt[d * 64 + ((c0 + 4) ^ sK)];
                const float qa[4] = {qv.x, qv.y, qv.z, qv.w};
#pragma unroll
                for (int r = 0; r < 4; r++) {
                    u64 qp2 = pack2(qa[r], qa[r]);
                    fma2(sac[r][0], qp2, k0.x);
                    fma2(sac[r][1], qp2, k0.y);
                    fma2(sac[r][2], qp2, k1.x);
                    fma2(sac[r][3], qp2, k1.y);
                }
            }

            const bool maskt = (j0 + 63 > q0);
            float ps[4][8];
#pragma unroll
            for (int r = 0; r < 4; r++) {
                float sv[8];
#pragma unroll
                for (int c = 0; c < 4; c++) {
                    float2 v = unpack2(sac[r][c]);
                    sv[2 * c] = v.x; sv[2 * c + 1] = v.y;
                }
                if (maskt) {
                    int rowg = q0 + i0 + r;
#pragma unroll
                    for (int cc = 0; cc < 8; cc++)
                        if (j0 + c0 + cc > rowg) sv[cc] = -1e9f;
                }
                float ml = sv[0];
#pragma unroll
                for (int cc = 1; cc < 8; cc++) ml = fmaxf(ml, sv[cc]);
                ml = fmaxf(ml, __shfl_xor_sync(0xffffffffu, ml, 1));
                ml = fmaxf(ml, __shfl_xor_sync(0xffffffffu, ml, 2));
                ml = fmaxf(ml, __shfl_xor_sync(0xffffffffu, ml, 4));
                float mn = fmaxf(mreg[r], ml);
                float a = ex2(mreg[r] - mn);
                mreg[r] = mn; alpha[r] = a;
                float rs = 0.f;
#pragma unroll
                for (int cc = 0; cc < 8; cc++) { ps[r][cc] = ex2(sv[cc] - mn); rs += ps[r][cc]; }
                rs += __shfl_xor_sync(0xffffffffu, rs, 1);
                rs += __shfl_xor_sync(0xffffffffu, rs, 2);
                rs += __shfl_xor_sync(0xffffffffu, rs, 4);
                lreg[r] = lreg[r] * a + rs;
            }
            {
                const int ip = i0 ^ (tx << 2);
#pragma unroll
                for (int cc = 0; cc < 8; cc++)
                    *(float4*)&Pt[(c0 + cc) * 128 + ip] =
                        make_float4(ps[0][cc], ps[1][cc], ps[2][cc], ps[3][cc]);
            }
#pragma unroll
            for (int r = 0; r < 4; r++) {
                u64 a2 = pack2(alpha[r], alpha[r]);
#pragma unroll
                for (int c = 0; c < 4; c++) O[r][c] = mul2(O[r][c], a2);
            }
            __syncthreads();

#pragma unroll
            for (int jo = 0; jo < 8; jo++) {
                const int sp = jo << 2;
#pragma unroll
                for (int ji = 0; ji < 8; ji++) {
                    const int j = jo * 8 + ji;
                    float4 pv = *(const float4*)&Pt[j * 128 + (i0 ^ sp)];
                    ulonglong2 v0 = *(const ulonglong2*)&Vs[j * 68 + (c0 ^ sK)];
                    ulonglong2 v1 = *(const ulonglong2*)&Vs[j * 68 + ((c0 + 4) ^ sK)];
                    const float pa[4] = {pv.x, pv.y, pv.z, pv.w};
#pragma unroll
                    for (int r = 0; r < 4; r++) {
                        u64 pp = pack2(pa[r], pa[r]);
                        fma2(O[r][0], pp, v0.x);
                        fma2(O[r][1], pp, v0.y);
                        fma2(O[r][2], pp, v1.x);
                        fma2(O[r][3], pp, v1.y);
                    }
                }
            }
        }

#pragma unroll
        for (int r = 0; r < 4; r++) {
            float linv = 1.0f / lreg[r];
            float2 v0 = unpack2(O[r][0]), v1 = unpack2(O[r][1]);
            float2 v2 = unpack2(O[r][2]), v3 = unpack2(O[r][3]);
            float* op = out + (rowbase + q0 + i0 + r) * HID + h * HD + c0;
            *(float4*)(op)     = make_float4(v0.x * linv, v0.y * linv, v1.x * linv, v1.y * linv);
            *(float4*)(op + 4) = make_float4(v2.x * linv, v2.y * linv, v3.x * linv, v3.y * linv);
        }
    }
}

// ================================ launch ===================================
extern "C" void kernel_launch(void* const* d_in, const int* in_sizes, int n_in,
                              void* d_out, int out_size)
{
    const float* hidden = (const float*)d_in[0];
    const float* Wqkv = (const float*)d_in[2];
    const float* Wo   = (const float*)d_in[3];
    float* out = (float*)d_out;

    float *qkv_ptr, *att_ptr;
    cudaGetSymbolAddress((void**)&qkv_ptr, g_qkv);
    cudaGetSymbolAddress((void**)&att_ptr, g_att);

    rope_tables_kernel<<<(S_LEN * 32 + 255) / 256, 256>>>();

    sgemm7<<<dim3(3 * HID / 128, ROWS / 128), 256>>>(hidden, Wqkv, qkv_ptr, ROWS, 3 * HID, HID);

    rope_apply2_kernel<<<(ROWS * 256) / 256, 256>>>();

    const int SMEM = ATTN_F * 4;
    cudaFuncSetAttribute(attn5_kernel, cudaFuncAttributeMaxDynamicSharedMemorySize, SMEM);
    dim3 g2(NT / 2, BATCH * NH);
    attn5_kernel<<<g2, 256, SMEM>>>(qkv_ptr, att_ptr);

    sgemm7<<<dim3(HID / 128, ROWS / 128), 256>>>(att_ptr, Wo, out, ROWS, HID, HID);
}

// round 13
// speedup vs baseline: 1.0688x; 1.0603x over previous
#include <cuda_runtime.h>
#include <cstdint>
#include <math.h>

#define S_LEN 2048
#define HID   1024
#define NH    16
#define HD    64
#define BATCH 2
#define ROWS  (BATCH * S_LEN)   // 4096
#define NT    (S_LEN / 128)     // 16 q-tiles

typedef unsigned long long u64;

// -------- scratch (static __device__ arrays; no allocation allowed) --------
__device__ float g_qkv[(size_t)ROWS * 3 * HID];  // [4096][3072]
__device__ float g_att[(size_t)ROWS * HID];      // [4096][1024]
__device__ float g_cos[S_LEN * 32];
__device__ float g_sin[S_LEN * 32];

// ======================= packed f32x2 helpers ==============================
__device__ __forceinline__ u64 pack2(float x, float y) {
    u64 r; asm("mov.b64 %0, {%1,%2};" : "=l"(r) : "f"(x), "f"(y)); return r;
}
__device__ __forceinline__ void fma2(u64& d, u64 a, u64 b) {
    asm("fma.rn.f32x2 %0, %1, %2, %0;" : "+l"(d) : "l"(a), "l"(b));
}
__device__ __forceinline__ u64 mul2(u64 a, u64 b) {
    u64 r; asm("mul.rn.f32x2 %0, %1, %2;" : "=l"(r) : "l"(a), "l"(b)); return r;
}
__device__ __forceinline__ float2 unpack2(u64 v) {
    float2 r; asm("mov.b64 {%0,%1}, %2;" : "=f"(r.x), "=f"(r.y) : "l"(v)); return r;
}
__device__ __forceinline__ float ex2(float x) {
    float r; asm("ex2.approx.f32 %0, %1;" : "=f"(r) : "f"(x)); return r;
}

// ============ f32x2 SGEMM (128x128x16) + optional fused RoPE ===============
// sgemm5 (measured best) with RoPE applied in the epilogue for q/k tiles.
__global__ __launch_bounds__(256, 2) void sgemm8(
    const float* __restrict__ A, const float* __restrict__ B,
    float* __restrict__ C, int M, int N, int K, int rope)
{
    __shared__ __align__(16) float As[16][132];
    __shared__ __align__(16) float Bs[16][128];

    const int tid = threadIdx.x;
    const int tx = tid & 15, ty = tid >> 4;
    const int m0 = blockIdx.y * 128, n0 = blockIdx.x * 128;
    const int s2 = ((tx >> 2) & 1) << 2;

    const int ar = tid & 127, akc = (tid >> 7) << 3;
    const int br = tid >> 5,  bnc = (tid & 31) << 2;
    const int bns = bnc ^ ((((bnc >> 5) & 1)) << 2);
    const float* Agp = A + (size_t)(m0 + ar) * K + akc;
    const float* Bgp = B + (size_t)br * N + n0 + bnc;

    u64 acc[8][4];
#pragma unroll
    for (int r = 0; r < 8; r++)
#pragma unroll
        for (int c = 0; c < 4; c++) acc[r][c] = pack2(0.f, 0.f);

    float4 pa0, pa1, pb0, pb1;
    const int T = K >> 4;

    pa0 = *(const float4*)(Agp);
    pa1 = *(const float4*)(Agp + 4);
    pb0 = *(const float4*)(Bgp);
    pb1 = *(const float4*)(Bgp + (size_t)8 * N);

    for (int t = 0; t < T; t++) {
        __syncthreads();
        {
            const float av[8] = {pa0.x, pa0.y, pa0.z, pa0.w, pa1.x, pa1.y, pa1.z, pa1.w};
#pragma unroll
            for (int e = 0; e < 8; e++) As[akc + e][ar] = av[e];
            *(float4*)&Bs[br][bns]     = pb0;
            *(float4*)&Bs[br + 8][bns] = pb1;
        }
        __syncthreads();

        if (t + 1 < T) {
            const int k0 = (t + 1) << 4;
            pa0 = *(const float4*)(Agp + k0);
            pa1 = *(const float4*)(Agp + k0 + 4);
            pb0 = *(const float4*)(Bgp + (size_t)k0 * N);
            pb1 = *(const float4*)(Bgp + (size_t)(k0 + 8) * N);
        }

#pragma unroll
        for (int kk = 0; kk < 16; kk++) {
            float4 a0 = *(const float4*)&As[kk][ty * 8];
            float4 a1 = *(const float4*)&As[kk][ty * 8 + 4];
            float4 b0 = *(const float4*)&Bs[kk][(tx * 8) ^ s2];
            float4 b1 = *(const float4*)&Bs[kk][(tx * 8 + 4) ^ s2];
            u64 bp[4] = {pack2(b0.x, b0.y), pack2(b0.z, b0.w),
                         pack2(b1.x, b1.y), pack2(b1.z, b1.w)};
            const float av[8] = {a0.x, a0.y, a0.z, a0.w, a1.x, a1.y, a1.z, a1.w};
#pragma unroll
            for (int r = 0; r < 8; r++) {
                u64 ap = pack2(av[r], av[r]);
#pragma unroll
                for (int c = 0; c < 4; c++) fma2(acc[r][c], ap, bp[c]);
            }
        }
    }

    // -------- epilogue: optional fused RoPE (q/k region only) --------
    const bool dorope = rope && (n0 < 2 * HID);
    const int jo = (tx & 3) << 3;                    // (tx*8) & 31
    const float sign = (tx & 4) ? 1.0f : -1.0f;      // high half: +sin, low: -sin

#pragma unroll
    for (int r = 0; r < 8; r++) {
        float v[8];
        {
            float2 q0 = unpack2(acc[r][0]), q1 = unpack2(acc[r][1]);
            float2 q2 = unpack2(acc[r][2]), q3 = unpack2(acc[r][3]);
            v[0] = q0.x; v[1] = q0.y; v[2] = q1.x; v[3] = q1.y;
            v[4] = q2.x; v[5] = q2.y; v[6] = q3.x; v[7] = q3.y;
        }
        if (dorope) {
            float pv[8];
#pragma unroll
            for (int e = 0; e < 8; e++)
                pv[e] = __shfl_xor_sync(0xffffffffu, v[e], 4);
            const int srow = (m0 + ty * 8 + r) & (S_LEN - 1);
            float4 c0v = *(const float4*)(g_cos + srow * 32 + jo);
            float4 c1v = *(const float4*)(g_cos + srow * 32 + jo + 4);
            float4 s0v = *(const float4*)(g_sin + srow * 32 + jo);
            float4 s1v = *(const float4*)(g_sin + srow * 32 + jo + 4);
            const float cc[8] = {c0v.x, c0v.y, c0v.z, c0v.w, c1v.x, c1v.y, c1v.z, c1v.w};
            const float ss[8] = {s0v.x, s0v.y, s0v.z, s0v.w, s1v.x, s1v.y, s1v.z, s1v.w};
#pragma unroll
            for (int e = 0; e < 8; e++)
                v[e] = v[e] * cc[e] + pv[e] * (sign * ss[e]);
        }
        float* crow = C + (size_t)(m0 + ty * 8 + r) * N + n0 + tx * 8;
        *(float4*)(crow)     = make_float4(v[0], v[1], v[2], v[3]);
        *(float4*)(crow + 4) = make_float4(v[4], v[5], v[6], v[7]);
    }
}

// ============================ RoPE tables ==================================
__global__ void rope_tables_kernel()
{
    int idx = blockIdx.x * blockDim.x + threadIdx.x;
    if (idx >= S_LEN * 32) return;
    int s = idx >> 5, j = idx & 31;
    double inv = exp(-((double)j / 32.0) * log(160000.0));
    double ang = (double)s * inv;
    g_cos[idx] = (float)cos(ang);
    g_sin[idx] = (float)sin(ang);
}

// ===== fused causal flash attention v5 (balanced + log2-domain softmax) ====
#define AQT 0
#define AKT 8192
#define AVS 12288
#define APT 16640
#define ATTN_F 24832          // 99328 bytes
#define QSCALE 0.18033688f    // 0.125 * log2(e)

__global__ __launch_bounds__(256, 2) void attn5_kernel(
    const float* __restrict__ qkv, float* __restrict__ out)
{
    extern __shared__ __align__(16) float sm[];
    float* Qt = sm + AQT;
    float* Kt = sm + AKT;
    float* Vs = sm + AVS;
    float* Pt = sm + APT;

    const int tid = threadIdx.x;
    const int tx = tid & 7, ty = tid >> 3;
    const int i0 = ty * 4, c0 = tx * 8;
    const int sK = (tx >> 2) << 2;
    const int bh = blockIdx.y;
    const int b = bh >> 4, h = bh & 15;
    const size_t rowbase = (size_t)b * S_LEN;
    const int qoff = h * HD, koff = HID + h * HD, voff = 2 * HID + h * HD;

    const int frq = tid & 127, fgq = tid >> 7;
    const int fr = tid & 63, fg = tid >> 6;
    const int jswz = fr ^ ((((fr >> 5) & 1)) << 2);
    const int vcs  = (fg >> 1) << 2;

#pragma unroll 1
    for (int pass = 0; pass < 2; pass++) {
        const int qt = pass ? (NT - 1 - (int)blockIdx.x) : (int)blockIdx.x;
        const int q0 = qt * 128;

        {
            const float* qp = qkv + (rowbase + q0 + frq) * 3072 + qoff + fgq * 32;
#pragma unroll
            for (int q = 0; q < 8; q++) {
                float4 v = *(const float4*)(qp + 4 * q);
                int d = fgq * 32 + 4 * q;
                Qt[(d + 0) * 128 + frq] = v.x * QSCALE;
                Qt[(d + 1) * 128 + frq] = v.y * QSCALE;
                Qt[(d + 2) * 128 + frq] = v.z * QSCALE;
                Qt[(d + 3) * 128 + frq] = v.w * QSCALE;
            }
        }

        float mreg[4], lreg[4], alpha[4];
        u64 O[4][4];
#pragma unroll
        for (int r = 0; r < 4; r++) {
            mreg[r] = -INFINITY; lreg[r] = 0.f;
#pragma unroll
            for (int c = 0; c < 4; c++) O[r][c] = pack2(0.f, 0.f);
        }

        for (int j0 = 0; j0 <= q0 + 64; j0 += 64) {
            __syncthreads();
            {
                const float* kp = qkv + (rowbase + j0 + fr) * 3072 + koff + fg * 16;
#pragma unroll
                for (int q = 0; q < 4; q++) {
                    float4 v = *(const float4*)(kp + 4 * q);
                    int d = fg * 16 + 4 * q;
                    Kt[(d + 0) * 64 + jswz] = v.x; Kt[(d + 1) * 64 + jswz] = v.y;
                    Kt[(d + 2) * 64 + jswz] = v.z; Kt[(d + 3) * 64 + jswz] = v.w;
                }
                const float* vp = qkv + (rowbase + j0 + fr) * 3072 + voff + fg * 16;
#pragma unroll
                for (int q = 0; q < 4; q++) {
                    int c = fg * 16 + 4 * q;
                    *(float4*)&Vs[fr * 68 + (c ^ vcs)] = *(const float4*)(vp + 4 * q);
                }
            }
            __syncthreads();

            u64 sac[4][4];
#pragma unroll
            for (int r = 0; r < 4; r++)
#pragma unroll
                for (int c = 0; c < 4; c++) sac[r][c] = pack2(0.f, 0.f);
#pragma unroll 4
            for (int d = 0; d < 64; d++) {
                float4 qv = *(const float4*)&Qt[d * 128 + i0];
                ulonglong2 k0 = *(const ulonglong2*)&Kt[d * 64 + (c0 ^ sK)];
                ulonglong2 k1 = *(const ulonglong2*)&Kt[d * 64 + ((c0 + 4) ^ sK)];
                const float qa[4] = {qv.x, qv.y, qv.z, qv.w};
#pragma unroll
                for (int r = 0; r < 4; r++) {
                    u64 qp2 = pack2(qa[r], qa[r]);
                    fma2(sac[r][0], qp2, k0.x);
                    fma2(sac[r][1], qp2, k0.y);
                    fma2(sac[r][2], qp2, k1.x);
                    fma2(sac[r][3], qp2, k1.y);
                }
            }

            const bool maskt = (j0 + 63 > q0);
            float ps[4][8];
#pragma unroll
            for (int r = 0; r < 4; r++) {
                float sv[8];
#pragma unroll
                for (int c = 0; c < 4; c++) {
                    float2 v = unpack2(sac[r][c]);
                    sv[2 * c] = v.x; sv[2 * c + 1] = v.y;
                }
                if (maskt) {
                    int rowg = q0 + i0 + r;
#pragma unroll
                    for (int cc = 0; cc < 8; cc++)
                        if (j0 + c0 + cc > rowg) sv[cc] = -1e9f;
                }
                float ml = sv[0];
#pragma unroll
                for (int cc = 1; cc < 8; cc++) ml = fmaxf(ml, sv[cc]);
                ml = fmaxf(ml, __shfl_xor_sync(0xffffffffu, ml, 1));
                ml = fmaxf(ml, __shfl_xor_sync(0xffffffffu, ml, 2));
                ml = fmaxf(ml, __shfl_xor_sync(0xffffffffu, ml, 4));
                float mn = fmaxf(mreg[r], ml);
                float a = ex2(mreg[r] - mn);
                mreg[r] = mn; alpha[r] = a;
                float rs = 0.f;
#pragma unroll
                for (int cc = 0; cc < 8; cc++) { ps[r][cc] = ex2(sv[cc] - mn); rs += ps[r][cc]; }
                rs += __shfl_xor_sync(0xffffffffu, rs, 1);
                rs += __shfl_xor_sync(0xffffffffu, rs, 2);
                rs += __shfl_xor_sync(0xffffffffu, rs, 4);
                lreg[r] = lreg[r] * a + rs;
            }
            {
                const int ip = i0 ^ (tx << 2);
#pragma unroll
                for (int cc = 0; cc < 8; cc++)
                    *(float4*)&Pt[(c0 + cc) * 128 + ip] =
                        make_float4(ps[0][cc], ps[1][cc], ps[2][cc], ps[3][cc]);
            }
#pragma unroll
            for (int r = 0; r < 4; r++) {
                u64 a2 = pack2(alpha[r], alpha[r]);
#pragma unroll
                for (int c = 0; c < 4; c++) O[r][c] = mul2(O[r][c], a2);
            }
            __syncthreads();

#pragma unroll
            for (int jo2 = 0; jo2 < 8; jo2++) {
                const int sp = jo2 << 2;
#pragma unroll
                for (int ji = 0; ji < 8; ji++) {
                    const int j = jo2 * 8 + ji;
                    float4 pv = *(const float4*)&Pt[j * 128 + (i0 ^ sp)];
                    ulonglong2 v0 = *(const ulonglong2*)&Vs[j * 68 + (c0 ^ sK)];
                    ulonglong2 v1 = *(const ulonglong2*)&Vs[j * 68 + ((c0 + 4) ^ sK)];
                    const float pa[4] = {pv.x, pv.y, pv.z, pv.w};
#pragma unroll
                    for (int r = 0; r < 4; r++) {
                        u64 pp = pack2(pa[r], pa[r]);
                        fma2(O[r][0], pp, v0.x);
                        fma2(O[r][1], pp, v0.y);
                        fma2(O[r][2], pp, v1.x);
                        fma2(O[r][3], pp, v1.y);
                    }
                }
            }
        }

#pragma unroll
        for (int r = 0; r < 4; r++) {
            float linv = 1.0f / lreg[r];
            float2 v0 = unpack2(O[r][0]), v1 = unpack2(O[r][1]);
            float2 v2 = unpack2(O[r][2]), v3 = unpack2(O[r][3]);
            float* op = out + (rowbase + q0 + i0 + r) * HID + h * HD + c0;
            *(float4*)(op)     = make_float4(v0.x * linv, v0.y * linv, v1.x * linv, v1.y * linv);
            *(float4*)(op + 4) = make_float4(v2.x * linv, v2.y * linv, v3.x * linv, v3.y * linv);
        }
    }
}

// ================================ launch ===================================
extern "C" void kernel_launch(void* const* d_in, const int* in_sizes, int n_in,
                              void* d_out, int out_size)
{
    const float* hidden = (const float*)d_in[0];
    const float* Wqkv = (const float*)d_in[2];
    const float* Wo   = (const float*)d_in[3];
    float* out = (float*)d_out;

    float *qkv_ptr, *att_ptr;
    cudaGetSymbolAddress((void**)&qkv_ptr, g_qkv);
    cudaGetSymbolAddress((void**)&att_ptr, g_att);

    rope_tables_kernel<<<(S_LEN * 32 + 255) / 256, 256>>>();

    // QKV GEMM with fused RoPE on q/k tiles
    sgemm8<<<dim3(3 * HID / 128, ROWS / 128), 256>>>(hidden, Wqkv, qkv_ptr, ROWS, 3 * HID, HID, 1);

    const int SMEM = ATTN_F * 4;
    cudaFuncSetAttribute(attn5_kernel, cudaFuncAttributeMaxDynamicSharedMemorySize, SMEM);
    dim3 g2(NT / 2, BATCH * NH);
    attn5_kernel<<<g2, 256, SMEM>>>(qkv_ptr, att_ptr);

    // output projection (no rope)
    sgemm8<<<dim3(HID / 128, ROWS / 128), 256>>>(att_ptr, Wo, out, ROWS, HID, HID, 0);
}

// round 14
// speedup vs baseline: 1.0949x; 1.0244x over previous
#include <cuda_runtime.h>
#include <cstdint>
#include <math.h>

#define S_LEN 2048
#define HID   1024
#define NH    16
#define HD    64
#define BATCH 2
#define ROWS  (BATCH * S_LEN)   // 4096
#define NT    (S_LEN / 128)     // 16 q-tiles

typedef unsigned long long u64;

// -------- scratch (static __device__ arrays; no allocation allowed) --------
__device__ float g_qkv[(size_t)ROWS * 3 * HID];  // [4096][3072]
__device__ float g_att[(size_t)ROWS * HID];      // [4096][1024]
__device__ float g_cos[S_LEN * 32];
__device__ float g_sin[S_LEN * 32];

// ======================= packed f32x2 helpers ==============================
__device__ __forceinline__ u64 pack2(float x, float y) {
    u64 r; asm("mov.b64 %0, {%1,%2};" : "=l"(r) : "f"(x), "f"(y)); return r;
}
__device__ __forceinline__ void fma2(u64& d, u64 a, u64 b) {
    asm("fma.rn.f32x2 %0, %1, %2, %0;" : "+l"(d) : "l"(a), "l"(b));
}
__device__ __forceinline__ u64 mul2(u64 a, u64 b) {
    u64 r; asm("mul.rn.f32x2 %0, %1, %2;" : "=l"(r) : "l"(a), "l"(b)); return r;
}
__device__ __forceinline__ float2 unpack2(u64 v) {
    float2 r; asm("mov.b64 {%0,%1}, %2;" : "=f"(r.x), "=f"(r.y) : "l"(v)); return r;
}
__device__ __forceinline__ float ex2(float x) {
    float r; asm("ex2.approx.f32 %0, %1;" : "=f"(r) : "f"(x)); return r;
}

// ============ f32x2 SGEMM (128x128x16) + optional fused RoPE ===============
// sgemm8 + B fragments read as ulonglong2 (adjacent-col pairs come pre-packed
// from LDS.128; kills 4 mov.b64 per kk — inner loop 48 -> 44 instructions).
__global__ __launch_bounds__(256, 2) void sgemm9(
    const float* __restrict__ A, const float* __restrict__ B,
    float* __restrict__ C, int M, int N, int K, int rope)
{
    __shared__ __align__(16) float As[16][132];
    __shared__ __align__(16) float Bs[16][128];

    const int tid = threadIdx.x;
    const int tx = tid & 15, ty = tid >> 4;
    const int m0 = blockIdx.y * 128, n0 = blockIdx.x * 128;
    const int s2 = ((tx >> 2) & 1) << 2;

    const int ar = tid & 127, akc = (tid >> 7) << 3;
    const int br = tid >> 5,  bnc = (tid & 31) << 2;
    const int bns = bnc ^ ((((bnc >> 5) & 1)) << 2);
    const float* Agp = A + (size_t)(m0 + ar) * K + akc;
    const float* Bgp = B + (size_t)br * N + n0 + bnc;

    u64 acc[8][4];
#pragma unroll
    for (int r = 0; r < 8; r++)
#pragma unroll
        for (int c = 0; c < 4; c++) acc[r][c] = pack2(0.f, 0.f);

    float4 pa0, pa1, pb0, pb1;
    const int T = K >> 4;

    pa0 = *(const float4*)(Agp);
    pa1 = *(const float4*)(Agp + 4);
    pb0 = *(const float4*)(Bgp);
    pb1 = *(const float4*)(Bgp + (size_t)8 * N);

    for (int t = 0; t < T; t++) {
        __syncthreads();
        {
            const float av[8] = {pa0.x, pa0.y, pa0.z, pa0.w, pa1.x, pa1.y, pa1.z, pa1.w};
#pragma unroll
            for (int e = 0; e < 8; e++) As[akc + e][ar] = av[e];
            *(float4*)&Bs[br][bns]     = pb0;
            *(float4*)&Bs[br + 8][bns] = pb1;
        }
        __syncthreads();

        if (t + 1 < T) {
            const int k0 = (t + 1) << 4;
            pa0 = *(const float4*)(Agp + k0);
            pa1 = *(const float4*)(Agp + k0 + 4);
            pb0 = *(const float4*)(Bgp + (size_t)k0 * N);
            pb1 = *(const float4*)(Bgp + (size_t)(k0 + 8) * N);
        }

#pragma unroll
        for (int kk = 0; kk < 16; kk++) {
            float4 a0 = *(const float4*)&As[kk][ty * 8];
            float4 a1 = *(const float4*)&As[kk][ty * 8 + 4];
            ulonglong2 bq0 = *(const ulonglong2*)&Bs[kk][(tx * 8) ^ s2];
            ulonglong2 bq1 = *(const ulonglong2*)&Bs[kk][(tx * 8 + 4) ^ s2];
            const u64 bp[4] = {bq0.x, bq0.y, bq1.x, bq1.y};
            const float av[8] = {a0.x, a0.y, a0.z, a0.w, a1.x, a1.y, a1.z, a1.w};
#pragma unroll
            for (int r = 0; r < 8; r++) {
                u64 ap = pack2(av[r], av[r]);
#pragma unroll
                for (int c = 0; c < 4; c++) fma2(acc[r][c], ap, bp[c]);
            }
        }
    }

    // -------- epilogue: optional fused RoPE (q/k region only) --------
    const bool dorope = rope && (n0 < 2 * HID);
    const int jo = (tx & 3) << 3;                    // (tx*8) & 31
    const float sign = (tx & 4) ? 1.0f : -1.0f;      // high half: +sin, low: -sin

#pragma unroll
    for (int r = 0; r < 8; r++) {
        float v[8];
        {
            float2 q0 = unpack2(acc[r][0]), q1 = unpack2(acc[r][1]);
            float2 q2 = unpack2(acc[r][2]), q3 = unpack2(acc[r][3]);
            v[0] = q0.x; v[1] = q0.y; v[2] = q1.x; v[3] = q1.y;
            v[4] = q2.x; v[5] = q2.y; v[6] = q3.x; v[7] = q3.y;
        }
        if (dorope) {
            float pv[8];
#pragma unroll
            for (int e = 0; e < 8; e++)
                pv[e] = __shfl_xor_sync(0xffffffffu, v[e], 4);
            const int srow = (m0 + ty * 8 + r) & (S_LEN - 1);
            float4 c0v = *(const float4*)(g_cos + srow * 32 + jo);
            float4 c1v = *(const float4*)(g_cos + srow * 32 + jo + 4);
            float4 s0v = *(const float4*)(g_sin + srow * 32 + jo);
            float4 s1v = *(const float4*)(g_sin + srow * 32 + jo + 4);
            const float cc[8] = {c0v.x, c0v.y, c0v.z, c0v.w, c1v.x, c1v.y, c1v.z, c1v.w};
            const float ss[8] = {s0v.x, s0v.y, s0v.z, s0v.w, s1v.x, s1v.y, s1v.z, s1v.w};
#pragma unroll
            for (int e = 0; e < 8; e++)
                v[e] = v[e] * cc[e] + pv[e] * (sign * ss[e]);
        }
        float* crow = C + (size_t)(m0 + ty * 8 + r) * N + n0 + tx * 8;
        *(float4*)(crow)     = make_float4(v[0], v[1], v[2], v[3]);
        *(float4*)(crow + 4) = make_float4(v[4], v[5], v[6], v[7]);
    }
}

// ============================ RoPE tables ==================================
__global__ void rope_tables_kernel()
{
    int idx = blockIdx.x * blockDim.x + threadIdx.x;
    if (idx >= S_LEN * 32) return;
    int s = idx >> 5, j = idx & 31;
    double inv = exp(-((double)j / 32.0) * log(160000.0));
    double ang = (double)s * inv;
    g_cos[idx] = (float)cos(ang);
    g_sin[idx] = (float)sin(ang);
}

// ===== fused causal flash attention v5 (balanced + log2-domain softmax) ====
#define AQT 0
#define AKT 8192
#define AVS 12288
#define APT 16640
#define ATTN_F 24832          // 99328 bytes
#define QSCALE 0.18033688f    // 0.125 * log2(e)

__global__ __launch_bounds__(256, 2) void attn5_kernel(
    const float* __restrict__ qkv, float* __restrict__ out)
{
    extern __shared__ __align__(16) float sm[];
    float* Qt = sm + AQT;
    float* Kt = sm + AKT;
    float* Vs = sm + AVS;
    float* Pt = sm + APT;

    const int tid = threadIdx.x;
    const int tx = tid & 7, ty = tid >> 3;
    const int i0 = ty * 4, c0 = tx * 8;
    const int sK = (tx >> 2) << 2;
    const int bh = blockIdx.y;
    const int b = bh >> 4, h = bh & 15;
    const size_t rowbase = (size_t)b * S_LEN;
    const int qoff = h * HD, koff = HID + h * HD, voff = 2 * HID + h * HD;

    const int frq = tid & 127, fgq = tid >> 7;
    const int fr = tid & 63, fg = tid >> 6;
    const int jswz = fr ^ ((((fr >> 5) & 1)) << 2);
    const int vcs  = (fg >> 1) << 2;

#pragma unroll 1
    for (int pass = 0; pass < 2; pass++) {
        const int qt = pass ? (NT - 1 - (int)blockIdx.x) : (int)blockIdx.x;
        const int q0 = qt * 128;

        {
            const float* qp = qkv + (rowbase + q0 + frq) * 3072 + qoff + fgq * 32;
#pragma unroll
            for (int q = 0; q < 8; q++) {
                float4 v = *(const float4*)(qp + 4 * q);
                int d = fgq * 32 + 4 * q;
                Qt[(d + 0) * 128 + frq] = v.x * QSCALE;
                Qt[(d + 1) * 128 + frq] = v.y * QSCALE;
                Qt[(d + 2) * 128 + frq] = v.z * QSCALE;
                Qt[(d + 3) * 128 + frq] = v.w * QSCALE;
            }
        }

        float mreg[4], lreg[4], alpha[4];
        u64 O[4][4];
#pragma unroll
        for (int r = 0; r < 4; r++) {
            mreg[r] = -INFINITY; lreg[r] = 0.f;
#pragma unroll
            for (int c = 0; c < 4; c++) O[r][c] = pack2(0.f, 0.f);
        }

        for (int j0 = 0; j0 <= q0 + 64; j0 += 64) {
            __syncthreads();
            {
                const float* kp = qkv + (rowbase + j0 + fr) * 3072 + koff + fg * 16;
#pragma unroll
                for (int q = 0; q < 4; q++) {
                    float4 v = *(const float4*)(kp + 4 * q);
                    int d = fg * 16 + 4 * q;
                    Kt[(d + 0) * 64 + jswz] = v.x; Kt[(d + 1) * 64 + jswz] = v.y;
                    Kt[(d + 2) * 64 + jswz] = v.z; Kt[(d + 3) * 64 + jswz] = v.w;
                }
                const float* vp = qkv + (rowbase + j0 + fr) * 3072 + voff + fg * 16;
#pragma unroll
                for (int q = 0; q < 4; q++) {
                    int c = fg * 16 + 4 * q;
                    *(float4*)&Vs[fr * 68 + (c ^ vcs)] = *(const float4*)(vp + 4 * q);
                }
            }
            __syncthreads();

            u64 sac[4][4];
#pragma unroll
            for (int r = 0; r < 4; r++)
#pragma unroll
                for (int c = 0; c < 4; c++) sac[r][c] = pack2(0.f, 0.f);
#pragma unroll 4
            for (int d = 0; d < 64; d++) {
                float4 qv = *(const float4*)&Qt[d * 128 + i0];
                ulonglong2 k0 = *(const ulonglong2*)&Kt[d * 64 + (c0 ^ sK)];
                ulonglong2 k1 = *(const ulonglong2*)&Kt[d * 64 + ((c0 + 4) ^ sK)];
                const float qa[4] = {qv.x, qv.y, qv.z, qv.w};
#pragma unroll
                for (int r = 0; r < 4; r++) {
                    u64 qp2 = pack2(qa[r], qa[r]);
                    fma2(sac[r][0], qp2, k0.x);
                    fma2(sac[r][1], qp2, k0.y);
                    fma2(sac[r][2], qp2, k1.x);
                    fma2(sac[r][3], qp2, k1.y);
                }
            }

            const bool maskt = (j0 + 63 > q0);
            float ps[4][8];
#pragma unroll
            for (int r = 0; r < 4; r++) {
                float sv[8];
#pragma unroll
                for (int c = 0; c < 4; c++) {
                    float2 v = unpack2(sac[r][c]);
                    sv[2 * c] = v.x; sv[2 * c + 1] = v.y;
                }
                if (maskt) {
                    int rowg = q0 + i0 + r;
#pragma unroll
                    for (int cc = 0; cc < 8; cc++)
                        if (j0 + c0 + cc > rowg) sv[cc] = -1e9f;
                }
                float ml = sv[0];
#pragma unroll
                for (int cc = 1; cc < 8; cc++) ml = fmaxf(ml, sv[cc]);
                ml = fmaxf(ml, __shfl_xor_sync(0xffffffffu, ml, 1));
                ml = fmaxf(ml, __shfl_xor_sync(0xffffffffu, ml, 2));
                ml = fmaxf(ml, __shfl_xor_sync(0xffffffffu, ml, 4));
                float mn = fmaxf(mreg[r], ml);
                float a = ex2(mreg[r] - mn);
                mreg[r] = mn; alpha[r] = a;
                float rs = 0.f;
#pragma unroll
                for (int cc = 0; cc < 8; cc++) { ps[r][cc] = ex2(sv[cc] - mn); rs += ps[r][cc]; }
                rs += __shfl_xor_sync(0xffffffffu, rs, 1);
                rs += __shfl_xor_sync(0xffffffffu, rs, 2);
                rs += __shfl_xor_sync(0xffffffffu, rs, 4);
                lreg[r] = lreg[r] * a + rs;
            }
            {
                const int ip = i0 ^ (tx << 2);
#pragma unroll
                for (int cc = 0; cc < 8; cc++)
                    *(float4*)&Pt[(c0 + cc) * 128 + ip] =
                        make_float4(ps[0][cc], ps[1][cc], ps[2][cc], ps[3][cc]);
            }
#pragma unroll
            for (int r = 0; r < 4; r++) {
                u64 a2 = pack2(alpha[r], alpha[r]);
#pragma unroll
                for (int c = 0; c < 4; c++) O[r][c] = mul2(O[r][c], a2);
            }
            __syncthreads();

#pragma unroll
            for (int jo2 = 0; jo2 < 8; jo2++) {
                const int sp = jo2 << 2;
#pragma unroll
                for (int ji = 0; ji < 8; ji++) {
                    const int j = jo2 * 8 + ji;
                    float4 pv = *(const float4*)&Pt[j * 128 + (i0 ^ sp)];
                    ulonglong2 v0 = *(const ulonglong2*)&Vs[j * 68 + (c0 ^ sK)];
                    ulonglong2 v1 = *(const ulonglong2*)&Vs[j * 68 + ((c0 + 4) ^ sK)];
                    const float pa[4] = {pv.x, pv.y, pv.z, pv.w};
#pragma unroll
                    for (int r = 0; r < 4; r++) {
                        u64 pp = pack2(pa[r], pa[r]);
                        fma2(O[r][0], pp, v0.x);
                        fma2(O[r][1], pp, v0.y);
                        fma2(O[r][2], pp, v1.x);
                        fma2(O[r][3], pp, v1.y);
                    }
                }
            }
        }

#pragma unroll
        for (int r = 0; r < 4; r++) {
            float linv = 1.0f / lreg[r];
            float2 v0 = unpack2(O[r][0]), v1 = unpack2(O[r][1]);
            float2 v2 = unpack2(O[r][2]), v3 = unpack2(O[r][3]);
            float* op = out + (rowbase + q0 + i0 + r) * HID + h * HD + c0;
            *(float4*)(op)     = make_float4(v0.x * linv, v0.y * linv, v1.x * linv, v1.y * linv);
            *(float4*)(op + 4) = make_float4(v2.x * linv, v2.y * linv, v3.x * linv, v3.y * linv);
        }
    }
}

// ================================ launch ===================================
extern "C" void kernel_launch(void* const* d_in, const int* in_sizes, int n_in,
                              void* d_out, int out_size)
{
    const float* hidden = (const float*)d_in[0];
    const float* Wqkv = (const float*)d_in[2];
    const float* Wo   = (const float*)d_in[3];
    float* out = (float*)d_out;

    float *qkv_ptr, *att_ptr;
    cudaGetSymbolAddress((void**)&qkv_ptr, g_qkv);
    cudaGetSymbolAddress((void**)&att_ptr, g_att);

    rope_tables_kernel<<<(S_LEN * 32 + 255) / 256, 256>>>();

    // QKV GEMM with fused RoPE on q/k tiles
    sgemm9<<<dim3(3 * HID / 128, ROWS / 128), 256>>>(hidden, Wqkv, qkv_ptr, ROWS, 3 * HID, HID, 1);

    const int SMEM = ATTN_F * 4;
    cudaFuncSetAttribute(attn5_kernel, cudaFuncAttributeMaxDynamicSharedMemorySize, SMEM);
    dim3 g2(NT / 2, BATCH * NH);
    attn5_kernel<<<g2, 256, SMEM>>>(qkv_ptr, att_ptr);

    // output projection (no rope)
    sgemm9<<<dim3(HID / 128, ROWS / 128), 256>>>(att_ptr, Wo, out, ROWS, HID, HID, 0);
}